// round 15
// baseline (speedup 1.0000x reference)
#include <cuda_runtime.h>
#include <cuda_fp16.h>
#include <math.h>
#include <stdint.h>

#define Bb   2
#define Ss   2048
#define Hh   1024
#define NHh  16
#define HDd  64
#define RDd  16
#define Ww   16
#define SCALE 0.125f

#define KP   1024
#define NIT  (KP / 32)

// ---------------- scratch (device globals: no allocations allowed) ----------
__device__ __half g_h_hs  [(size_t)Bb * Ss * Hh];
__device__ __half g_h_A   [(size_t)Bb * Ss * Hh];
__device__ __half g_h_oh  [(size_t)Bb * Ss * Hh];
__device__ __half g_h_Wqkv[(size_t)3 * Hh * Hh];
__device__ __half g_h_Wqka[(size_t)2 * Hh * Hh];    // [Wqa ; Wka] stacked
__device__ __half g_h_Wd  [(size_t)Hh * Hh];

__device__ __half g_hQw[(size_t)Bb * NHh * Ss * HDd];
__device__ __half g_hKw[(size_t)Bb * NHh * Ss * HDd];
__device__ __half g_hVw[(size_t)Bb * NHh * Ss * HDd];

__device__ __half g_hQ [(size_t)Bb * NHh * Ss * HDd];   // [bh, s, 64]
__device__ __half g_hK [(size_t)Bb * NHh * Ss * HDd];   // [bh, s, 64]
__device__ __half g_hVt[(size_t)Bb * NHh * HDd * Ss];   // [bh*64+d, s]

// =================== helpers ================================================
__device__ __forceinline__ uint32_t smem_u32(const void* p) {
    uint32_t a;
    asm("{ .reg .u64 t; cvta.to.shared.u64 t, %1; cvt.u32.u64 %0, t; }" : "=r"(a) : "l"(p));
    return a;
}
__device__ __forceinline__ void cp_async16(void* s, const void* g) {
    uint32_t sa = smem_u32(s);
    asm volatile("cp.async.ca.shared.global [%0], [%1], 16;" :: "r"(sa), "l"(g));
}
#define CP_COMMIT() asm volatile("cp.async.commit_group;" ::: "memory")
#define CP_WAIT1()  asm volatile("cp.async.wait_group 1;" ::: "memory")
#define CP_WAIT0()  asm volatile("cp.async.wait_group 0;" ::: "memory")

__device__ __forceinline__ void ldmat_x4(uint32_t* r, uint32_t addr) {
    asm volatile("ldmatrix.sync.aligned.m8n8.x4.shared.b16 {%0,%1,%2,%3}, [%4];"
        : "=r"(r[0]), "=r"(r[1]), "=r"(r[2]), "=r"(r[3]) : "r"(addr));
}
__device__ __forceinline__ void mma_f16(float* d, const uint32_t* a, const uint32_t* b) {
    asm volatile(
        "mma.sync.aligned.m16n8k16.row.col.f32.f16.f16.f32 "
        "{%0,%1,%2,%3}, {%4,%5,%6,%7}, {%8,%9}, {%0,%1,%2,%3};"
        : "+f"(d[0]), "+f"(d[1]), "+f"(d[2]), "+f"(d[3])
        : "r"(a[0]), "r"(a[1]), "r"(a[2]), "r"(a[3]), "r"(b[0]), "r"(b[1]));
}
__device__ __forceinline__ uint32_t pack_h2(float x, float y) {
    __half2 t = __floats2half2_rn(x, y);
    return *(uint32_t*)&t;
}

// ====== fp32 -> fp16 flat convert ===========================================
__global__ void conv_h(const float* __restrict__ X, __half* __restrict__ Y, int n4)
{
    int i = blockIdx.x * blockDim.x + threadIdx.x;
    if (i >= n4) return;
    int base = i << 2;
    float4 v = *(const float4*)(X + base);
    ((__half2*)(Y + base))[0] = __floats2half2_rn(v.x, v.y);
    ((__half2*)(Y + base))[1] = __floats2half2_rn(v.z, v.w);
}

// =================== shared GEMM mainloop (computes acc[4][4][4]) ===========
#define GEMM_BODY(A2, B2)                                                        \
    __shared__ __align__(16) __half sm[2][2][128][40];                           \
    const int tid = threadIdx.x;                                                 \
    const int wid = tid >> 5;                                                    \
    const int lane = tid & 31;                                                   \
    const int bm = blockIdx.y * 128;                                             \
    const int bn = blockIdx.x * 128;                                             \
    const int wm = wid & 1;                                                      \
    const int wn = wid >> 1;                                                     \
    float acc[4][4][4];                                                          \
    _Pragma("unroll")                                                            \
    for (int mi = 0; mi < 4; mi++)                                               \
        _Pragma("unroll")                                                        \
        for (int ni = 0; ni < 4; ni++)                                           \
            _Pragma("unroll")                                                    \
            for (int q = 0; q < 4; q++) acc[mi][ni][q] = 0.f;                    \
    auto load_tile = [&](int buf, int k0) {                                      \
        _Pragma("unroll")                                                        \
        for (int i = 0; i < 2; i++) {                                            \
            int c = tid + i * 256;                                               \
            int r = c >> 2;                                                      \
            int kk = (c & 3) * 8;                                                \
            cp_async16(&sm[buf][0][r][kk], A2 + (size_t)(bm + r) * KP + k0 + kk);\
            cp_async16(&sm[buf][1][r][kk], B2 + (size_t)(bn + r) * KP + k0 + kk);\
        }                                                                        \
        CP_COMMIT();                                                             \
    };                                                                           \
    load_tile(0, 0);                                                             \
    for (int it = 0; it < NIT; it++) {                                           \
        const int buf = it & 1;                                                  \
        if (it + 1 < NIT) { load_tile(buf ^ 1, (it + 1) * 32); CP_WAIT1(); }     \
        else              { CP_WAIT0(); }                                        \
        __syncthreads();                                                         \
        _Pragma("unroll")                                                        \
        for (int ks = 0; ks < 2; ks++) {                                         \
            uint32_t af[4][4];                                                   \
            _Pragma("unroll")                                                    \
            for (int mi = 0; mi < 4; mi++) {                                     \
                uint32_t addr = smem_u32(                                        \
                    &sm[buf][0][wm * 64 + mi * 16 + (lane & 15)][ks * 16 + (lane >> 4) * 8]); \
                ldmat_x4(af[mi], addr);                                          \
            }                                                                    \
            uint32_t bf[2][4];                                                   \
            _Pragma("unroll")                                                    \
            for (int g = 0; g < 2; g++) {                                        \
                uint32_t addr = smem_u32(                                        \
                    &sm[buf][1][wn * 32 + g * 16 + (lane & 7) + ((lane >> 4) & 1) * 8] \
                               [ks * 16 + ((lane >> 3) & 1) * 8]);               \
                ldmat_x4(bf[g], addr);                                           \
            }                                                                    \
            _Pragma("unroll")                                                    \
            for (int mi = 0; mi < 4; mi++)                                       \
                _Pragma("unroll")                                                \
                for (int ni = 0; ni < 4; ni++) {                                 \
                    uint32_t bb[2] = {bf[ni >> 1][(ni & 1) * 2],                 \
                                      bf[ni >> 1][(ni & 1) * 2 + 1]};            \
                    mma_f16(acc[mi][ni], af[mi], bb);                            \
                }                                                                \
        }                                                                        \
        __syncthreads();                                                         \
    }

// ======== generic GEMM: fp32 out + bias =====================================
__global__ void __launch_bounds__(256) hmma_gemm(
    const __half* __restrict__ A2, const __half* __restrict__ B2,
    const float* __restrict__ bias, float* __restrict__ C, int M, int N)
{
    GEMM_BODY(A2, B2)
#pragma unroll
    for (int mi = 0; mi < 4; mi++) {
        int row0 = bm + wm * 64 + mi * 16 + (lane >> 2);
#pragma unroll
        for (int ni = 0; ni < 4; ni++) {
            int col = bn + wn * 32 + ni * 8 + (lane & 3) * 2;
            float b0 = bias[col];
            float b1 = bias[col + 1];
            float2 v0 = {acc[mi][ni][0] + b0, acc[mi][ni][1] + b1};
            float2 v1 = {acc[mi][ni][2] + b0, acc[mi][ni][3] + b1};
            *(float2*)(C + (size_t)row0 * N + col)       = v0;
            *(float2*)(C + (size_t)(row0 + 8) * N + col) = v1;
        }
    }
}

// ======== qkv GEMM: bias + RoPE fused, writes fp16 head-major q/k/v =========
__global__ void __launch_bounds__(256) hmma_gemm_qkv(
    const __half* __restrict__ A2, const __half* __restrict__ B2,
    const float* __restrict__ bqkv,
    __half* __restrict__ Qw, __half* __restrict__ Kw, __half* __restrict__ Vw)
{
    GEMM_BODY(A2, B2)
    const int which = bn >> 10;            // 0=q, 1=k, 2=v
    const int cb = bn & 1023;
    __half* dst = (which == 0) ? Qw : ((which == 1) ? Kw : Vw);
    const bool rope_warp = (which < 2) && ((wn & 1) == 0);

#pragma unroll
    for (int mi = 0; mi < 4; mi++) {
        int row0 = bm + wm * 64 + mi * 16 + (lane >> 2);
        int b = row0 >> 11;
        int s = row0 & 2047;

        float vals[4][4];
#pragma unroll
        for (int ni = 0; ni < 4; ni++) {
            int col = bn + wn * 32 + ni * 8 + (lane & 3) * 2;
            float b0 = bqkv[col];
            float b1 = bqkv[col + 1];
            vals[ni][0] = acc[mi][ni][0] + b0;
            vals[ni][1] = acc[mi][ni][1] + b1;
            vals[ni][2] = acc[mi][ni][2] + b0;
            vals[ni][3] = acc[mi][ni][3] + b1;
        }

        if (rope_warp) {
#pragma unroll
            for (int q = 0; q < 4; q++) {
                int i = (lane & 3) * 2 + (q & 1);          // freq index 0..7
                int ss = s + ((q >> 1) ? 8 : 0);
                float inv_freq = powf(10000.f, -(float)i / 8.f);
                float ang = (float)ss * inv_freq;
                float sn, cs;
                sincosf(ang, &sn, &cs);
                float x1 = vals[0][q], x2 = vals[1][q];
                vals[0][q] = x1 * cs - x2 * sn;
                vals[1][q] = x2 * cs + x1 * sn;
            }
        }

#pragma unroll
        for (int ni = 0; ni < 4; ni++) {
            int col = cb + wn * 32 + ni * 8 + (lane & 3) * 2;
            int hh = col >> 6;
            int d = col & 63;
            size_t or0 = ((size_t)(b * NHh + hh) * Ss + s) * 64 + d;
            *(uint32_t*)(dst + or0)          = pack_h2(vals[ni][0], vals[ni][1]);
            *(uint32_t*)(dst + or0 + 8 * 64) = pack_h2(vals[ni][2], vals[ni][3]);
        }
    }
}

// ======== fused qa/ka GEMM: epilogue -> hQ/hK fp16 head-major ===============
__global__ void __launch_bounds__(256) hmma_gemm_qk(
    const __half* __restrict__ A2, const __half* __restrict__ B2,
    const float* __restrict__ bqa, const float* __restrict__ bka,
    __half* __restrict__ Qd, __half* __restrict__ Kd)
{
    GEMM_BODY(A2, B2)
    const bool isK = (bn >= 1024);
    const float* bias = isK ? bka : bqa;
    __half* dst = isK ? Kd : Qd;
    const int cb = isK ? bn - 1024 : bn;

#pragma unroll
    for (int mi = 0; mi < 4; mi++) {
        int row0 = bm + wm * 64 + mi * 16 + (lane >> 2);
        int b = row0 >> 11;
        int s = row0 & 2047;
#pragma unroll
        for (int ni = 0; ni < 4; ni++) {
            int col = cb + wn * 32 + ni * 8 + (lane & 3) * 2;
            int hh = col >> 6;
            int d = col & 63;
            size_t or0 = ((size_t)(b * NHh + hh) * Ss + s) * 64 + d;
            float b0 = bias[col];
            float b1 = bias[col + 1];
            *(uint32_t*)(dst + or0) = pack_h2(acc[mi][ni][0] + b0, acc[mi][ni][1] + b1);
            *(uint32_t*)(dst + or0 + 8 * 64) =
                pack_h2(acc[mi][ni][2] + b0, acc[mi][ni][3] + b1);
        }
    }
}

// ------ tiled sliding-window attention (fp16 in) -> Ah (fp16 flat) + Vt -----
__global__ void __launch_bounds__(256) window_attn(
    const __half* __restrict__ Qw, const __half* __restrict__ Kw,
    const __half* __restrict__ Vw,
    __half* __restrict__ Ah, __half* __restrict__ Vt)
{
    __shared__ __half Ksm[79][64];
    __shared__ __half Vsm[79][64];
    __shared__ float  Osm[64][65];
    const int q0 = blockIdx.x * 64;
    const int h  = blockIdx.y;
    const int b  = blockIdx.z;
    const int tid = threadIdx.x;
    const int wid = tid >> 5, lane = tid & 31;
    const size_t bhS = ((size_t)(b * NHh + h)) * Ss;

    for (int i = tid; i < 79 * 8; i += 256) {
        int row = i >> 3, c8 = (i & 7) * 8;
        int s = q0 - 15 + row;
        if (s >= 0) {
            *(uint4*)&Ksm[row][c8] = *(const uint4*)(Kw + (bhS + s) * 64 + c8);
            *(uint4*)&Vsm[row][c8] = *(const uint4*)(Vw + (bhS + s) * 64 + c8);
        }
    }
    __syncthreads();

    for (int qq = 0; qq < 8; qq++) {
        int sq = q0 + wid * 8 + qq;
        int rbase = wid * 8 + qq;
        float qv0 = __half2float(Qw[(bhS + sq) * 64 + lane]);
        float qv1 = __half2float(Qw[(bhS + sq) * 64 + lane + 32]);

        float sc[Ww];
#pragma unroll
        for (int w = 0; w < Ww; w++) {
            int idx = sq - (Ww - 1) + w;
            float p = qv0 * __half2float(Ksm[rbase + w][lane])
                    + qv1 * __half2float(Ksm[rbase + w][lane + 32]);
#pragma unroll
            for (int off = 16; off; off >>= 1)
                p += __shfl_xor_sync(0xffffffffu, p, off);
            sc[w] = (idx >= 0) ? p * SCALE : -1e30f;
        }

        float mx = sc[0];
#pragma unroll
        for (int w = 1; w < Ww; w++) mx = fmaxf(mx, sc[w]);
        float lsum = 0.f;
#pragma unroll
        for (int w = 0; w < Ww; w++) { float e = __expf(sc[w] - mx); sc[w] = e; lsum += e; }
        float inv = 1.f / lsum;

        float o0 = 0.f, o1 = 0.f;
#pragma unroll
        for (int w = 0; w < Ww; w++) {
            int idx = sq - (Ww - 1) + w;
            if (idx >= 0) {
                o0 += sc[w] * __half2float(Vsm[rbase + w][lane]);
                o1 += sc[w] * __half2float(Vsm[rbase + w][lane + 32]);
            }
        }
        Osm[wid * 8 + qq][lane]      = o0 * inv;
        Osm[wid * 8 + qq][lane + 32] = o1 * inv;
    }
    __syncthreads();

    for (int i = tid; i < 512; i += 256) {
        int r = i >> 3, c8 = (i & 7) * 8;
        uint4 outv;
        uint32_t* ov = (uint32_t*)&outv;
#pragma unroll
        for (int t = 0; t < 4; t++)
            ov[t] = pack_h2(Osm[r][c8 + 2 * t], Osm[r][c8 + 2 * t + 1]);
        *(uint4*)(Ah + ((size_t)(b * Ss + q0 + r)) * Hh + h * 64 + c8) = outv;
    }

    {
        int d = tid >> 2;
        int k0 = (tid & 3) * 16;
        uint32_t wh[8];
#pragma unroll
        for (int t = 0; t < 8; t++)
            wh[t] = pack_h2(Osm[k0 + 2 * t][d], Osm[k0 + 2 * t + 1][d]);
        size_t off = ((size_t)(b * NHh + h) * 64 + d) * Ss + q0 + k0;
        *(uint4*)(Vt + off)     = make_uint4(wh[0], wh[1], wh[2], wh[3]);
        *(uint4*)(Vt + off + 8) = make_uint4(wh[4], wh[5], wh[6], wh[7]);
    }
}

// -------- HMMA flash attention fp16: 128-row Q tiles, 8 warps ---------------
// smem (half): Q[128][72] | 2 x { K[64][72] | V[64][72] }
#define FQE   9216
#define FBUF  9216
#define FQ(r, c)      fsm[(r) * 72 + (c)]
#define FK(bf, r, c)  fsm[FQE + (bf) * FBUF + (r) * 72 + (c)]
#define FV(bf, r, c)  fsm[FQE + (bf) * FBUF + 4608 + (r) * 72 + (c)]
#define FLASH_SMEM ((FQE + 2 * FBUF) * 2)

__global__ void __launch_bounds__(256, 3) flash_hmma(
    const __half* __restrict__ Qd, const __half* __restrict__ Kd,
    const __half* __restrict__ Vt, __half* __restrict__ Oh)
{
    extern __shared__ __half fsm[];
    const int qt = (int)gridDim.x - 1 - (int)blockIdx.x;   // long first
    const int h  = blockIdx.y;
    const int b  = blockIdx.z;
    const int tid = threadIdx.x;
    const int w = tid >> 5;
    const int lane = tid & 31;
    const int wrow = w * 16;           // warp's rows within 128-row tile

    const size_t bhS  = ((size_t)(b * NHh + h)) * Ss;
    const size_t bh64 = ((size_t)(b * NHh + h)) * 64;
    const __half* Qsrc = Qd + (bhS + qt * 128) * 64;

    auto load_kv = [&](int bf, int kt) {
        const __half* Ksrc = Kd + (bhS + kt * 64) * 64;
        const __half* Vsrc = Vt + bh64 * Ss + kt * 64;
        for (int i = tid; i < 512; i += 256) {
            int r = i >> 3, c = (i & 7) * 8;
            cp_async16(&FK(bf, r, c), Ksrc + (size_t)r * 64 + c);
            cp_async16(&FV(bf, r, c), Vsrc + (size_t)r * Ss + c);
        }
        CP_COMMIT();
    };

    // load Q tile (128 rows)
    for (int i = tid; i < 1024; i += 256) {
        int r = i >> 3, c = (i & 7) * 8;
        cp_async16(&FQ(r, c), Qsrc + (size_t)r * 64 + c);
    }
    CP_COMMIT();
    load_kv(0, 0);

    float acc[8][4];
#pragma unroll
    for (int j = 0; j < 8; j++)
#pragma unroll
        for (int q = 0; q < 4; q++) acc[j][q] = 0.f;
    float m0 = -1e30f, m1 = -1e30f, l0 = 0.f, l1 = 0.f;

    const int nkt = 2 * qt + 2;        // k tiles covering rows [0, qt*128+127]
    for (int kt = 0; kt < nkt; kt++) {
        const int bf = kt & 1;
        __syncthreads();
        if (kt + 1 < nkt) { load_kv(bf ^ 1, kt + 1); CP_WAIT1(); }
        else              { CP_WAIT0(); }
        __syncthreads();

        float sv[8][4];
#pragma unroll
        for (int j = 0; j < 8; j++)
#pragma unroll
            for (int q = 0; q < 4; q++) sv[j][q] = 0.f;

#pragma unroll
        for (int ks = 0; ks < 4; ks++) {
            uint32_t a[4];
            ldmat_x4(a, smem_u32(&FQ(wrow + (lane & 15), ks * 16 + (lane >> 4) * 8)));
#pragma unroll
            for (int g = 0; g < 4; g++) {
                uint32_t bfr[4];
                ldmat_x4(bfr, smem_u32(&FK(bf, g * 16 + (lane & 7) + ((lane >> 4) & 1) * 8,
                                           ks * 16 + ((lane >> 3) & 1) * 8)));
                { uint32_t bb[2] = {bfr[0], bfr[1]}; mma_f16(sv[2 * g], a, bb); }
                { uint32_t bb[2] = {bfr[2], bfr[3]}; mma_f16(sv[2 * g + 1], a, bb); }
            }
        }

#pragma unroll
        for (int j = 0; j < 8; j++)
#pragma unroll
            for (int q = 0; q < 4; q++) sv[j][q] *= SCALE;

        // causal mask for tiles that can cross the diagonal
        if (kt >= 2 * qt) {
            int rg0 = qt * 128 + wrow + (lane >> 2);      // global row (lower 8-row grp)
            int cbase = kt * 64 + (lane & 3) * 2;          // global col base
#pragma unroll
            for (int j = 0; j < 8; j++) {
                int c0 = cbase + j * 8;
                if (c0     > rg0)     sv[j][0] = -1e30f;
                if (c0 + 1 > rg0)     sv[j][1] = -1e30f;
                if (c0     > rg0 + 8) sv[j][2] = -1e30f;
                if (c0 + 1 > rg0 + 8) sv[j][3] = -1e30f;
            }
        }

        float rm0 = -1e30f, rm1 = -1e30f;
#pragma unroll
        for (int j = 0; j < 8; j++) {
            rm0 = fmaxf(rm0, fmaxf(sv[j][0], sv[j][1]));
            rm1 = fmaxf(rm1, fmaxf(sv[j][2], sv[j][3]));
        }
        rm0 = fmaxf(rm0, __shfl_xor_sync(0xffffffffu, rm0, 1));
        rm0 = fmaxf(rm0, __shfl_xor_sync(0xffffffffu, rm0, 2));
        rm1 = fmaxf(rm1, __shfl_xor_sync(0xffffffffu, rm1, 1));
        rm1 = fmaxf(rm1, __shfl_xor_sync(0xffffffffu, rm1, 2));
        float mn0 = fmaxf(m0, rm0), mn1 = fmaxf(m1, rm1);
        float c0 = __expf(m0 - mn0), c1 = __expf(m1 - mn1);
        float rs0 = 0.f, rs1 = 0.f;
#pragma unroll
        for (int j = 0; j < 8; j++) {
            sv[j][0] = __expf(sv[j][0] - mn0); rs0 += sv[j][0];
            sv[j][1] = __expf(sv[j][1] - mn0); rs0 += sv[j][1];
            sv[j][2] = __expf(sv[j][2] - mn1); rs1 += sv[j][2];
            sv[j][3] = __expf(sv[j][3] - mn1); rs1 += sv[j][3];
        }
        rs0 += __shfl_xor_sync(0xffffffffu, rs0, 1);
        rs0 += __shfl_xor_sync(0xffffffffu, rs0, 2);
        rs1 += __shfl_xor_sync(0xffffffffu, rs1, 1);
        rs1 += __shfl_xor_sync(0xffffffffu, rs1, 2);
        l0 = l0 * c0 + rs0; l1 = l1 * c1 + rs1;
#pragma unroll
        for (int j = 0; j < 8; j++) {
            acc[j][0] *= c0; acc[j][1] *= c0;
            acc[j][2] *= c1; acc[j][3] *= c1;
        }
        m0 = mn0; m1 = mn1;

        uint32_t phi[4][4];
#pragma unroll
        for (int kb = 0; kb < 4; kb++) {
            int j0 = 2 * kb, j1 = 2 * kb + 1;
            phi[kb][0] = pack_h2(sv[j0][0], sv[j0][1]);
            phi[kb][1] = pack_h2(sv[j0][2], sv[j0][3]);
            phi[kb][2] = pack_h2(sv[j1][0], sv[j1][1]);
            phi[kb][3] = pack_h2(sv[j1][2], sv[j1][3]);
        }

#pragma unroll
        for (int g = 0; g < 4; g++) {
#pragma unroll
            for (int kb = 0; kb < 4; kb++) {
                uint32_t vh[4];
                uint32_t rowa = g * 16 + (lane & 7) + ((lane >> 4) & 1) * 8;
                uint32_t cola = kb * 16 + ((lane >> 3) & 1) * 8;
                ldmat_x4(vh, smem_u32(&FV(bf, rowa, cola)));
                { uint32_t bb[2] = {vh[0], vh[1]}; mma_f16(acc[2 * g], phi[kb], bb); }
                { uint32_t bb[2] = {vh[2], vh[3]}; mma_f16(acc[2 * g + 1], phi[kb], bb); }
            }
        }
    }

    float i0 = 1.f / l0, i1 = 1.f / l1;
    int r0 = qt * 128 + wrow + (lane >> 2);
    size_t ro = ((size_t)b * Ss + r0) * Hh + h * 64;
#pragma unroll
    for (int j = 0; j < 8; j++) {
        int cc = j * 8 + (lane & 3) * 2;
        *(uint32_t*)(Oh + ro + cc) = pack_h2(acc[j][0] * i0, acc[j][1] * i0);
        *(uint32_t*)(Oh + ro + (size_t)8 * Hh + cc) =
            pack_h2(acc[j][2] * i1, acc[j][3] * i1);
    }
}

// ---------------- launch -----------------------------------------------------
extern "C" void kernel_launch(void* const* d_in, const int* in_sizes, int n_in,
                              void* d_out, int out_size)
{
    const float* hs   = (const float*)d_in[0];
    const float* Wqkv = (const float*)d_in[1];
    const float* bqkv = (const float*)d_in[2];
    const float* Wqa  = (const float*)d_in[3];
    const float* bqa  = (const float*)d_in[4];
    const float* Wka  = (const float*)d_in[5];
    const float* bka  = (const float*)d_in[6];
    const float* Wd   = (const float*)d_in[7];
    const float* bd   = (const float*)d_in[8];
    float* out = (float*)d_out;

    __half *h_hs, *h_A, *h_oh, *h_Wqkv, *h_Wqka, *h_Wd;
    __half *hQw, *hKw, *hVw, *hQ, *hK, *hVt;
    cudaGetSymbolAddress((void**)&h_hs,   g_h_hs);
    cudaGetSymbolAddress((void**)&h_A,    g_h_A);
    cudaGetSymbolAddress((void**)&h_oh,   g_h_oh);
    cudaGetSymbolAddress((void**)&h_Wqkv, g_h_Wqkv);
    cudaGetSymbolAddress((void**)&h_Wqka, g_h_Wqka);
    cudaGetSymbolAddress((void**)&h_Wd,   g_h_Wd);
    cudaGetSymbolAddress((void**)&hQw, g_hQw);
    cudaGetSymbolAddress((void**)&hKw, g_hKw);
    cudaGetSymbolAddress((void**)&hVw, g_hVw);
    cudaGetSymbolAddress((void**)&hQ,  g_hQ);
    cudaGetSymbolAddress((void**)&hK,  g_hK);
    cudaGetSymbolAddress((void**)&hVt, g_hVt);

    cudaFuncSetAttribute(flash_hmma, cudaFuncAttributeMaxDynamicSharedMemorySize,
                         FLASH_SMEM);

    const int M = Bb * Ss;          // 4096

    auto conv = [](const float* x, __half* y, int elems) {
        int n4 = elems / 4;
        conv_h<<<(n4 + 255) / 256, 256>>>(x, y, n4);
    };

    conv(hs,   h_hs,   M * Hh);
    conv(Wqkv, h_Wqkv, 3 * Hh * Hh);
    conv(Wqa,  h_Wqka, Hh * Hh);
    conv(Wka,  h_Wqka + (size_t)Hh * Hh, Hh * Hh);
    conv(Wd,   h_Wd,   Hh * Hh);

    // 1) qkv GEMM + bias + RoPE -> fp16 head-major q/k/v
    hmma_gemm_qkv<<<dim3(3 * Hh / 128, M / 128), 256>>>(
        h_hs, h_Wqkv, bqkv, hQw, hKw, hVw);

    // 2) sliding-window attention -> h_A (flat fp16) + hVt (transposed fp16)
    window_attn<<<dim3(Ss / 64, NHh, Bb), 256>>>(hQw, hKw, hVw, h_A, hVt);

    // 3) fused qa/ka GEMM -> hQ/hK
    hmma_gemm_qk<<<dim3(2 * Hh / 128, M / 128), 256>>>(h_A, h_Wqka, bqa, bka, hQ, hK);

    // 4) full causal attention (HMMA fp16, 128-row Q tiles) -> h_oh
    flash_hmma<<<dim3(Ss / 128, NHh, Bb), 256, FLASH_SMEM>>>(hQ, hK, hVt, h_oh);

    // 5) out = h_oh @ Wd^T + bd
    hmma_gemm<<<dim3(Hh / 128, M / 128), 256>>>(h_oh, h_Wd, bd, out, M, Hh);
}

// round 16
// speedup vs baseline: 1.1103x; 1.1103x over previous
#include <cuda_runtime.h>
#include <cuda_fp16.h>
#include <math.h>
#include <stdint.h>

#define Bb   2
#define Ss   2048
#define Hh   1024
#define NHh  16
#define HDd  64
#define RDd  16
#define Ww   16
#define SCALE 0.125f

#define KP   1024
#define NIT  (KP / 32)

// ---------------- scratch (device globals: no allocations allowed) ----------
__device__ __half g_h_hs  [(size_t)Bb * Ss * Hh];
__device__ __half g_h_A   [(size_t)Bb * Ss * Hh];
__device__ __half g_h_oh  [(size_t)Bb * Ss * Hh];
__device__ __half g_h_Wqkv[(size_t)3 * Hh * Hh];
__device__ __half g_h_Wqka[(size_t)2 * Hh * Hh];    // [Wqa ; Wka] stacked
__device__ __half g_h_Wd  [(size_t)Hh * Hh];

__device__ __half g_hQw[(size_t)Bb * NHh * Ss * HDd];
__device__ __half g_hKw[(size_t)Bb * NHh * Ss * HDd];
__device__ __half g_hVw[(size_t)Bb * NHh * Ss * HDd];

__device__ __half g_hQ [(size_t)Bb * NHh * Ss * HDd];   // [bh, s, 64]
__device__ __half g_hK [(size_t)Bb * NHh * Ss * HDd];   // [bh, s, 64]
__device__ __half g_hVt[(size_t)Bb * NHh * HDd * Ss];   // [bh*64+d, s]

// =================== helpers ================================================
__device__ __forceinline__ uint32_t smem_u32(const void* p) {
    uint32_t a;
    asm("{ .reg .u64 t; cvta.to.shared.u64 t, %1; cvt.u32.u64 %0, t; }" : "=r"(a) : "l"(p));
    return a;
}
__device__ __forceinline__ void cp_async16(void* s, const void* g) {
    uint32_t sa = smem_u32(s);
    asm volatile("cp.async.ca.shared.global [%0], [%1], 16;" :: "r"(sa), "l"(g));
}
#define CP_COMMIT() asm volatile("cp.async.commit_group;" ::: "memory")
#define CP_WAIT1()  asm volatile("cp.async.wait_group 1;" ::: "memory")
#define CP_WAIT0()  asm volatile("cp.async.wait_group 0;" ::: "memory")

__device__ __forceinline__ void ldmat_x4(uint32_t* r, uint32_t addr) {
    asm volatile("ldmatrix.sync.aligned.m8n8.x4.shared.b16 {%0,%1,%2,%3}, [%4];"
        : "=r"(r[0]), "=r"(r[1]), "=r"(r[2]), "=r"(r[3]) : "r"(addr));
}
__device__ __forceinline__ void mma_f16(float* d, const uint32_t* a, const uint32_t* b) {
    asm volatile(
        "mma.sync.aligned.m16n8k16.row.col.f32.f16.f16.f32 "
        "{%0,%1,%2,%3}, {%4,%5,%6,%7}, {%8,%9}, {%0,%1,%2,%3};"
        : "+f"(d[0]), "+f"(d[1]), "+f"(d[2]), "+f"(d[3])
        : "r"(a[0]), "r"(a[1]), "r"(a[2]), "r"(a[3]), "r"(b[0]), "r"(b[1]));
}
__device__ __forceinline__ uint32_t pack_h2(float x, float y) {
    __half2 t = __floats2half2_rn(x, y);
    return *(uint32_t*)&t;
}

// ====== batched fp32 -> fp16 convert (all 5 operands in one launch) =========
// segment boundaries in float4 units:
//   hs: 0..1048575 | Wqkv: ..1835007 | Wqa: ..2097151 | Wka: ..2359295 | Wd: ..2621439
__global__ void conv_all(const float* __restrict__ hs, const float* __restrict__ Wqkv,
                         const float* __restrict__ Wqa, const float* __restrict__ Wka,
                         const float* __restrict__ Wd)
{
    int i = blockIdx.x * blockDim.x + threadIdx.x;
    if (i >= 2621440) return;
    const float* src;
    __half* dst;
    int off;
    if (i < 1048576)      { src = hs;   dst = g_h_hs;   off = i; }
    else if (i < 1835008) { src = Wqkv; dst = g_h_Wqkv; off = i - 1048576; }
    else if (i < 2097152) { src = Wqa;  dst = g_h_Wqka; off = i - 1835008; }
    else if (i < 2359296) { src = Wka;  dst = g_h_Wqka + (size_t)Hh * Hh / 1; off = i - 2097152; }
    else                  { src = Wd;   dst = g_h_Wd;   off = i - 2359296; }
    int base = off << 2;
    float4 v = *(const float4*)(src + base);
    ((__half2*)(dst + base))[0] = __floats2half2_rn(v.x, v.y);
    ((__half2*)(dst + base))[1] = __floats2half2_rn(v.z, v.w);
}

// =================== shared GEMM mainloop (computes acc[4][4][4]) ===========
#define GEMM_BODY(A2, B2)                                                        \
    __shared__ __align__(16) __half sm[2][2][128][40];                           \
    const int tid = threadIdx.x;                                                 \
    const int wid = tid >> 5;                                                    \
    const int lane = tid & 31;                                                   \
    const int bm = blockIdx.y * 128;                                             \
    const int bn = blockIdx.x * 128;                                             \
    const int wm = wid & 1;                                                      \
    const int wn = wid >> 1;                                                     \
    float acc[4][4][4];                                                          \
    _Pragma("unroll")                                                            \
    for (int mi = 0; mi < 4; mi++)                                               \
        _Pragma("unroll")                                                        \
        for (int ni = 0; ni < 4; ni++)                                           \
            _Pragma("unroll")                                                    \
            for (int q = 0; q < 4; q++) acc[mi][ni][q] = 0.f;                    \
    auto load_tile = [&](int buf, int k0) {                                      \
        _Pragma("unroll")                                                        \
        for (int i = 0; i < 2; i++) {                                            \
            int c = tid + i * 256;                                               \
            int r = c >> 2;                                                      \
            int kk = (c & 3) * 8;                                                \
            cp_async16(&sm[buf][0][r][kk], A2 + (size_t)(bm + r) * KP + k0 + kk);\
            cp_async16(&sm[buf][1][r][kk], B2 + (size_t)(bn + r) * KP + k0 + kk);\
        }                                                                        \
        CP_COMMIT();                                                             \
    };                                                                           \
    load_tile(0, 0);                                                             \
    for (int it = 0; it < NIT; it++) {                                           \
        const int buf = it & 1;                                                  \
        if (it + 1 < NIT) { load_tile(buf ^ 1, (it + 1) * 32); CP_WAIT1(); }     \
        else              { CP_WAIT0(); }                                        \
        __syncthreads();                                                         \
        _Pragma("unroll")                                                        \
        for (int ks = 0; ks < 2; ks++) {                                         \
            uint32_t af[4][4];                                                   \
            _Pragma("unroll")                                                    \
            for (int mi = 0; mi < 4; mi++) {                                     \
                uint32_t addr = smem_u32(                                        \
                    &sm[buf][0][wm * 64 + mi * 16 + (lane & 15)][ks * 16 + (lane >> 4) * 8]); \
                ldmat_x4(af[mi], addr);                                          \
            }                                                                    \
            uint32_t bf[2][4];                                                   \
            _Pragma("unroll")                                                    \
            for (int g = 0; g < 2; g++) {                                        \
                uint32_t addr = smem_u32(                                        \
                    &sm[buf][1][wn * 32 + g * 16 + (lane & 7) + ((lane >> 4) & 1) * 8] \
                               [ks * 16 + ((lane >> 3) & 1) * 8]);               \
                ldmat_x4(bf[g], addr);                                           \
            }                                                                    \
            _Pragma("unroll")                                                    \
            for (int mi = 0; mi < 4; mi++)                                       \
                _Pragma("unroll")                                                \
                for (int ni = 0; ni < 4; ni++) {                                 \
                    uint32_t bb[2] = {bf[ni >> 1][(ni & 1) * 2],                 \
                                      bf[ni >> 1][(ni & 1) * 2 + 1]};            \
                    mma_f16(acc[mi][ni], af[mi], bb);                            \
                }                                                                \
        }                                                                        \
        __syncthreads();                                                         \
    }

// ======== generic GEMM: fp32 out + bias =====================================
__global__ void __launch_bounds__(256) hmma_gemm(
    const __half* __restrict__ A2, const __half* __restrict__ B2,
    const float* __restrict__ bias, float* __restrict__ C, int M, int N)
{
    GEMM_BODY(A2, B2)
#pragma unroll
    for (int mi = 0; mi < 4; mi++) {
        int row0 = bm + wm * 64 + mi * 16 + (lane >> 2);
#pragma unroll
        for (int ni = 0; ni < 4; ni++) {
            int col = bn + wn * 32 + ni * 8 + (lane & 3) * 2;
            float b0 = bias[col];
            float b1 = bias[col + 1];
            float2 v0 = {acc[mi][ni][0] + b0, acc[mi][ni][1] + b1};
            float2 v1 = {acc[mi][ni][2] + b0, acc[mi][ni][3] + b1};
            *(float2*)(C + (size_t)row0 * N + col)       = v0;
            *(float2*)(C + (size_t)(row0 + 8) * N + col) = v1;
        }
    }
}

// ======== qkv GEMM: bias + RoPE fused, writes fp16 head-major q/k/v =========
__global__ void __launch_bounds__(256) hmma_gemm_qkv(
    const __half* __restrict__ A2, const __half* __restrict__ B2,
    const float* __restrict__ bqkv,
    __half* __restrict__ Qw, __half* __restrict__ Kw, __half* __restrict__ Vw)
{
    GEMM_BODY(A2, B2)
    const int which = bn >> 10;            // 0=q, 1=k, 2=v
    const int cb = bn & 1023;
    __half* dst = (which == 0) ? Qw : ((which == 1) ? Kw : Vw);
    const bool rope_warp = (which < 2) && ((wn & 1) == 0);

#pragma unroll
    for (int mi = 0; mi < 4; mi++) {
        int row0 = bm + wm * 64 + mi * 16 + (lane >> 2);
        int b = row0 >> 11;
        int s = row0 & 2047;

        float vals[4][4];
#pragma unroll
        for (int ni = 0; ni < 4; ni++) {
            int col = bn + wn * 32 + ni * 8 + (lane & 3) * 2;
            float b0 = bqkv[col];
            float b1 = bqkv[col + 1];
            vals[ni][0] = acc[mi][ni][0] + b0;
            vals[ni][1] = acc[mi][ni][1] + b1;
            vals[ni][2] = acc[mi][ni][2] + b0;
            vals[ni][3] = acc[mi][ni][3] + b1;
        }

        if (rope_warp) {
#pragma unroll
            for (int q = 0; q < 4; q++) {
                int i = (lane & 3) * 2 + (q & 1);          // freq index 0..7
                int ss = s + ((q >> 1) ? 8 : 0);
                float inv_freq = powf(10000.f, -(float)i / 8.f);
                float ang = (float)ss * inv_freq;
                float sn, cs;
                sincosf(ang, &sn, &cs);
                float x1 = vals[0][q], x2 = vals[1][q];
                vals[0][q] = x1 * cs - x2 * sn;
                vals[1][q] = x2 * cs + x1 * sn;
            }
        }

#pragma unroll
        for (int ni = 0; ni < 4; ni++) {
            int col = cb + wn * 32 + ni * 8 + (lane & 3) * 2;
            int hh = col >> 6;
            int d = col & 63;
            size_t or0 = ((size_t)(b * NHh + hh) * Ss + s) * 64 + d;
            *(uint32_t*)(dst + or0)          = pack_h2(vals[ni][0], vals[ni][1]);
            *(uint32_t*)(dst + or0 + 8 * 64) = pack_h2(vals[ni][2], vals[ni][3]);
        }
    }
}

// ======== fused qa/ka GEMM: epilogue -> hQ/hK fp16 head-major ===============
__global__ void __launch_bounds__(256) hmma_gemm_qk(
    const __half* __restrict__ A2, const __half* __restrict__ B2,
    const float* __restrict__ bqa, const float* __restrict__ bka,
    __half* __restrict__ Qd, __half* __restrict__ Kd)
{
    GEMM_BODY(A2, B2)
    const bool isK = (bn >= 1024);
    const float* bias = isK ? bka : bqa;
    __half* dst = isK ? Kd : Qd;
    const int cb = isK ? bn - 1024 : bn;

#pragma unroll
    for (int mi = 0; mi < 4; mi++) {
        int row0 = bm + wm * 64 + mi * 16 + (lane >> 2);
        int b = row0 >> 11;
        int s = row0 & 2047;
#pragma unroll
        for (int ni = 0; ni < 4; ni++) {
            int col = cb + wn * 32 + ni * 8 + (lane & 3) * 2;
            int hh = col >> 6;
            int d = col & 63;
            size_t or0 = ((size_t)(b * NHh + hh) * Ss + s) * 64 + d;
            float b0 = bias[col];
            float b1 = bias[col + 1];
            *(uint32_t*)(dst + or0) = pack_h2(acc[mi][ni][0] + b0, acc[mi][ni][1] + b1);
            *(uint32_t*)(dst + or0 + 8 * 64) =
                pack_h2(acc[mi][ni][2] + b0, acc[mi][ni][3] + b1);
        }
    }
}

// ------ tiled sliding-window attention (fp16 in) -> Ah (fp16 flat) + Vt -----
__global__ void __launch_bounds__(256) window_attn(
    const __half* __restrict__ Qw, const __half* __restrict__ Kw,
    const __half* __restrict__ Vw,
    __half* __restrict__ Ah, __half* __restrict__ Vt)
{
    __shared__ __half Ksm[79][64];
    __shared__ __half Vsm[79][64];
    __shared__ float  Osm[64][65];
    const int q0 = blockIdx.x * 64;
    const int h  = blockIdx.y;
    const int b  = blockIdx.z;
    const int tid = threadIdx.x;
    const int wid = tid >> 5, lane = tid & 31;
    const size_t bhS = ((size_t)(b * NHh + h)) * Ss;

    for (int i = tid; i < 79 * 8; i += 256) {
        int row = i >> 3, c8 = (i & 7) * 8;
        int s = q0 - 15 + row;
        if (s >= 0) {
            *(uint4*)&Ksm[row][c8] = *(const uint4*)(Kw + (bhS + s) * 64 + c8);
            *(uint4*)&Vsm[row][c8] = *(const uint4*)(Vw + (bhS + s) * 64 + c8);
        }
    }
    __syncthreads();

    for (int qq = 0; qq < 8; qq++) {
        int sq = q0 + wid * 8 + qq;
        int rbase = wid * 8 + qq;
        float qv0 = __half2float(Qw[(bhS + sq) * 64 + lane]);
        float qv1 = __half2float(Qw[(bhS + sq) * 64 + lane + 32]);

        float sc[Ww];
#pragma unroll
        for (int w = 0; w < Ww; w++) {
            int idx = sq - (Ww - 1) + w;
            float p = qv0 * __half2float(Ksm[rbase + w][lane])
                    + qv1 * __half2float(Ksm[rbase + w][lane + 32]);
#pragma unroll
            for (int off = 16; off; off >>= 1)
                p += __shfl_xor_sync(0xffffffffu, p, off);
            sc[w] = (idx >= 0) ? p * SCALE : -1e30f;
        }

        float mx = sc[0];
#pragma unroll
        for (int w = 1; w < Ww; w++) mx = fmaxf(mx, sc[w]);
        float lsum = 0.f;
#pragma unroll
        for (int w = 0; w < Ww; w++) { float e = __expf(sc[w] - mx); sc[w] = e; lsum += e; }
        float inv = 1.f / lsum;

        float o0 = 0.f, o1 = 0.f;
#pragma unroll
        for (int w = 0; w < Ww; w++) {
            int idx = sq - (Ww - 1) + w;
            if (idx >= 0) {
                o0 += sc[w] * __half2float(Vsm[rbase + w][lane]);
                o1 += sc[w] * __half2float(Vsm[rbase + w][lane + 32]);
            }
        }
        Osm[wid * 8 + qq][lane]      = o0 * inv;
        Osm[wid * 8 + qq][lane + 32] = o1 * inv;
    }
    __syncthreads();

    for (int i = tid; i < 512; i += 256) {
        int r = i >> 3, c8 = (i & 7) * 8;
        uint4 outv;
        uint32_t* ov = (uint32_t*)&outv;
#pragma unroll
        for (int t = 0; t < 4; t++)
            ov[t] = pack_h2(Osm[r][c8 + 2 * t], Osm[r][c8 + 2 * t + 1]);
        *(uint4*)(Ah + ((size_t)(b * Ss + q0 + r)) * Hh + h * 64 + c8) = outv;
    }

    {
        int d = tid >> 2;
        int k0 = (tid & 3) * 16;
        uint32_t wh[8];
#pragma unroll
        for (int t = 0; t < 8; t++)
            wh[t] = pack_h2(Osm[k0 + 2 * t][d], Osm[k0 + 2 * t + 1][d]);
        size_t off = ((size_t)(b * NHh + h) * 64 + d) * Ss + q0 + k0;
        *(uint4*)(Vt + off)     = make_uint4(wh[0], wh[1], wh[2], wh[3]);
        *(uint4*)(Vt + off + 8) = make_uint4(wh[4], wh[5], wh[6], wh[7]);
    }
}

// -------- HMMA flash attention fp16 (64-row Q tiles), Q frags hoisted -------
// smem (half): Q[64][72] | 2 x { K[64][72] | V[64][72] }
#define FBUF 9216
#define FQ(r, c)      fsm[(r) * 72 + (c)]
#define FK(bf, r, c)  fsm[4608 + (bf) * FBUF + (r) * 72 + (c)]
#define FV(bf, r, c)  fsm[4608 + (bf) * FBUF + 4608 + (r) * 72 + (c)]
#define FLASH_SMEM ((4608 + 2 * FBUF) * 2)

__global__ void __launch_bounds__(128, 4) flash_hmma(
    const __half* __restrict__ Qd, const __half* __restrict__ Kd,
    const __half* __restrict__ Vt, __half* __restrict__ Oh)
{
    extern __shared__ __half fsm[];
    const int qt = (int)gridDim.x - 1 - (int)blockIdx.x;
    const int h  = blockIdx.y;
    const int b  = blockIdx.z;
    const int tid = threadIdx.x;
    const int w = tid >> 5;
    const int lane = tid & 31;
    const int wrow = w * 16;

    const size_t bhS  = ((size_t)(b * NHh + h)) * Ss;
    const size_t bh64 = ((size_t)(b * NHh + h)) * 64;
    const __half* Qsrc = Qd + (bhS + qt * 64) * 64;

    auto load_kv = [&](int bf, int kt) {
        const __half* Ksrc = Kd + (bhS + kt * 64) * 64;
        const __half* Vsrc = Vt + bh64 * Ss + kt * 64;
        for (int i = tid; i < 512; i += 128) {
            int r = i >> 3, c = (i & 7) * 8;
            cp_async16(&FK(bf, r, c), Ksrc + (size_t)r * 64 + c);
            cp_async16(&FV(bf, r, c), Vsrc + (size_t)r * Ss + c);
        }
        CP_COMMIT();
    };

    for (int i = tid; i < 512; i += 128) {
        int r = i >> 3, c = (i & 7) * 8;
        cp_async16(&FQ(r, c), Qsrc + (size_t)r * 64 + c);
    }
    CP_COMMIT();
    load_kv(0, 0);

    // hoist Q fragments (invariant across k-tiles)
    CP_WAIT1();          // Q group complete (kv0 may still be in flight)
    __syncthreads();
    uint32_t qf[4][4];
#pragma unroll
    for (int ks = 0; ks < 4; ks++)
        ldmat_x4(qf[ks], smem_u32(&FQ(wrow + (lane & 15), ks * 16 + (lane >> 4) * 8)));

    float acc[8][4];
#pragma unroll
    for (int j = 0; j < 8; j++)
#pragma unroll
        for (int q = 0; q < 4; q++) acc[j][q] = 0.f;
    float m0 = -1e30f, m1 = -1e30f, l0 = 0.f, l1 = 0.f;

    for (int kt = 0; kt <= qt; kt++) {
        const int bf = kt & 1;
        __syncthreads();
        if (kt < qt) { load_kv(bf ^ 1, kt + 1); CP_WAIT1(); }
        else         { CP_WAIT0(); }
        __syncthreads();

        float sv[8][4];
#pragma unroll
        for (int j = 0; j < 8; j++)
#pragma unroll
            for (int q = 0; q < 4; q++) sv[j][q] = 0.f;

#pragma unroll
        for (int ks = 0; ks < 4; ks++) {
#pragma unroll
            for (int g = 0; g < 4; g++) {
                uint32_t bfr[4];
                ldmat_x4(bfr, smem_u32(&FK(bf, g * 16 + (lane & 7) + ((lane >> 4) & 1) * 8,
                                           ks * 16 + ((lane >> 3) & 1) * 8)));
                { uint32_t bb[2] = {bfr[0], bfr[1]}; mma_f16(sv[2 * g], qf[ks], bb); }
                { uint32_t bb[2] = {bfr[2], bfr[3]}; mma_f16(sv[2 * g + 1], qf[ks], bb); }
            }
        }

#pragma unroll
        for (int j = 0; j < 8; j++)
#pragma unroll
            for (int q = 0; q < 4; q++) sv[j][q] *= SCALE;

        if (kt == qt) {
            int rb0 = wrow + (lane >> 2);
            int cb  = (lane & 3) * 2;
#pragma unroll
            for (int j = 0; j < 8; j++) {
                int c0 = j * 8 + cb;
                if (c0     > rb0)     sv[j][0] = -1e30f;
                if (c0 + 1 > rb0)     sv[j][1] = -1e30f;
                if (c0     > rb0 + 8) sv[j][2] = -1e30f;
                if (c0 + 1 > rb0 + 8) sv[j][3] = -1e30f;
            }
        }

        float rm0 = -1e30f, rm1 = -1e30f;
#pragma unroll
        for (int j = 0; j < 8; j++) {
            rm0 = fmaxf(rm0, fmaxf(sv[j][0], sv[j][1]));
            rm1 = fmaxf(rm1, fmaxf(sv[j][2], sv[j][3]));
        }
        rm0 = fmaxf(rm0, __shfl_xor_sync(0xffffffffu, rm0, 1));
        rm0 = fmaxf(rm0, __shfl_xor_sync(0xffffffffu, rm0, 2));
        rm1 = fmaxf(rm1, __shfl_xor_sync(0xffffffffu, rm1, 1));
        rm1 = fmaxf(rm1, __shfl_xor_sync(0xffffffffu, rm1, 2));
        float mn0 = fmaxf(m0, rm0), mn1 = fmaxf(m1, rm1);
        float c0 = __expf(m0 - mn0), c1 = __expf(m1 - mn1);
        float rs0 = 0.f, rs1 = 0.f;
#pragma unroll
        for (int j = 0; j < 8; j++) {
            sv[j][0] = __expf(sv[j][0] - mn0); rs0 += sv[j][0];
            sv[j][1] = __expf(sv[j][1] - mn0); rs0 += sv[j][1];
            sv[j][2] = __expf(sv[j][2] - mn1); rs1 += sv[j][2];
            sv[j][3] = __expf(sv[j][3] - mn1); rs1 += sv[j][3];
        }
        rs0 += __shfl_xor_sync(0xffffffffu, rs0, 1);
        rs0 += __shfl_xor_sync(0xffffffffu, rs0, 2);
        rs1 += __shfl_xor_sync(0xffffffffu, rs1, 1);
        rs1 += __shfl_xor_sync(0xffffffffu, rs1, 2);
        l0 = l0 * c0 + rs0; l1 = l1 * c1 + rs1;
#pragma unroll
        for (int j = 0; j < 8; j++) {
            acc[j][0] *= c0; acc[j][1] *= c0;
            acc[j][2] *= c1; acc[j][3] *= c1;
        }
        m0 = mn0; m1 = mn1;

        uint32_t phi[4][4];
#pragma unroll
        for (int kb = 0; kb < 4; kb++) {
            int j0 = 2 * kb, j1 = 2 * kb + 1;
            phi[kb][0] = pack_h2(sv[j0][0], sv[j0][1]);
            phi[kb][1] = pack_h2(sv[j0][2], sv[j0][3]);
            phi[kb][2] = pack_h2(sv[j1][0], sv[j1][1]);
            phi[kb][3] = pack_h2(sv[j1][2], sv[j1][3]);
        }

#pragma unroll
        for (int g = 0; g < 4; g++) {
#pragma unroll
            for (int kb = 0; kb < 4; kb++) {
                uint32_t vh[4];
                uint32_t rowa = g * 16 + (lane & 7) + ((lane >> 4) & 1) * 8;
                uint32_t cola = kb * 16 + ((lane >> 3) & 1) * 8;
                ldmat_x4(vh, smem_u32(&FV(bf, rowa, cola)));
                { uint32_t bb[2] = {vh[0], vh[1]}; mma_f16(acc[2 * g], phi[kb], bb); }
                { uint32_t bb[2] = {vh[2], vh[3]}; mma_f16(acc[2 * g + 1], phi[kb], bb); }
            }
        }
    }

    float i0 = 1.f / l0, i1 = 1.f / l1;
    int r0 = qt * 64 + wrow + (lane >> 2);
    size_t ro = ((size_t)b * Ss + r0) * Hh + h * 64;
#pragma unroll
    for (int j = 0; j < 8; j++) {
        int cc = j * 8 + (lane & 3) * 2;
        *(uint32_t*)(Oh + ro + cc) = pack_h2(acc[j][0] * i0, acc[j][1] * i0);
        *(uint32_t*)(Oh + ro + (size_t)8 * Hh + cc) =
            pack_h2(acc[j][2] * i1, acc[j][3] * i1);
    }
}

// ---------------- launch -----------------------------------------------------
extern "C" void kernel_launch(void* const* d_in, const int* in_sizes, int n_in,
                              void* d_out, int out_size)
{
    const float* hs   = (const float*)d_in[0];
    const float* Wqkv = (const float*)d_in[1];
    const float* bqkv = (const float*)d_in[2];
    const float* Wqa  = (const float*)d_in[3];
    const float* bqa  = (const float*)d_in[4];
    const float* Wka  = (const float*)d_in[5];
    const float* bka  = (const float*)d_in[6];
    const float* Wd   = (const float*)d_in[7];
    const float* bd   = (const float*)d_in[8];
    float* out = (float*)d_out;

    __half *h_hs, *h_A, *h_oh, *h_Wqkv, *h_Wqka, *h_Wd;
    __half *hQw, *hKw, *hVw, *hQ, *hK, *hVt;
    cudaGetSymbolAddress((void**)&h_hs,   g_h_hs);
    cudaGetSymbolAddress((void**)&h_A,    g_h_A);
    cudaGetSymbolAddress((void**)&h_oh,   g_h_oh);
    cudaGetSymbolAddress((void**)&h_Wqkv, g_h_Wqkv);
    cudaGetSymbolAddress((void**)&h_Wqka, g_h_Wqka);
    cudaGetSymbolAddress((void**)&h_Wd,   g_h_Wd);
    cudaGetSymbolAddress((void**)&hQw, g_hQw);
    cudaGetSymbolAddress((void**)&hKw, g_hKw);
    cudaGetSymbolAddress((void**)&hVw, g_hVw);
    cudaGetSymbolAddress((void**)&hQ,  g_hQ);
    cudaGetSymbolAddress((void**)&hK,  g_hK);
    cudaGetSymbolAddress((void**)&hVt, g_hVt);

    cudaFuncSetAttribute(flash_hmma, cudaFuncAttributeMaxDynamicSharedMemorySize,
                         FLASH_SMEM);

    const int M = Bb * Ss;          // 4096

    // 0) all fp32->fp16 conversions in one launch
    conv_all<<<(2621440 + 255) / 256, 256>>>(hs, Wqkv, Wqa, Wka, Wd);

    // 1) qkv GEMM + bias + RoPE -> fp16 head-major q/k/v
    hmma_gemm_qkv<<<dim3(3 * Hh / 128, M / 128), 256>>>(
        h_hs, h_Wqkv, bqkv, hQw, hKw, hVw);

    // 2) sliding-window attention -> h_A (flat fp16) + hVt (transposed fp16)
    window_attn<<<dim3(Ss / 64, NHh, Bb), 256>>>(hQw, hKw, hVw, h_A, hVt);

    // 3) fused qa/ka GEMM -> hQ/hK
    hmma_gemm_qk<<<dim3(2 * Hh / 128, M / 128), 256>>>(h_A, h_Wqka, bqa, bka, hQ, hK);

    // 4) full causal attention (HMMA fp16, 64-row Q tiles) -> h_oh
    flash_hmma<<<dim3(Ss / 64, NHh, Bb), 128, FLASH_SMEM>>>(hQ, hK, hVt, h_oh);

    // 5) out = h_oh @ Wd^T + bd
    hmma_gemm<<<dim3(Hh / 128, M / 128), 256>>>(h_oh, h_Wd, bd, out, M, Hh);
}